// round 1
// baseline (speedup 1.0000x reference)
#include <cuda_runtime.h>
#include <math.h>

// Shapes (fixed for this problem)
#define Hd 1024
#define Fd 4096
#define Ed 8
#define Td 512      // capacity == number of active buffered rows per expert
#define OUT_TOK 2048

// Scratch (static __device__ globals: allocation-free per harness rules)
__device__ float g_buf [Ed * Td * Hd];   // 16 MB  dispatched activations
__device__ float g_hmid[Ed * Td * Fd];   // 64 MB  GEMM1+GELU output
__device__ float g_obuf[Ed * Td * Hd];   // 16 MB  GEMM2 output
__device__ int   g_order[Td][Ed];        // per-token experts sorted by score desc
__device__ float g_score[Td][Ed];        // normalized scores in rank order

// ---------------------------------------------------------------------------
// Gating: one warp per token. logits = x[t] @ Wg + bg ; softmax ; stable
// descending sort (lowest index wins ties, matching jax.lax.top_k);
// normalize by (sum + 1e-9).
// ---------------------------------------------------------------------------
__global__ void gate_kernel(const float* __restrict__ x,
                            const float* __restrict__ Wg,
                            const float* __restrict__ bg) {
    int warp = threadIdx.x >> 5;
    int lane = threadIdx.x & 31;
    int t = blockIdx.x * 8 + warp;
    if (t >= Td) return;

    const float* xr = x + (size_t)t * Hd;
    float acc[Ed];
#pragma unroll
    for (int e = 0; e < Ed; e++) acc[e] = 0.f;

    for (int h = lane; h < Hd; h += 32) {
        float xv = xr[h];
        const float* wr = Wg + (size_t)h * Ed;
#pragma unroll
        for (int e = 0; e < Ed; e++) acc[e] += xv * wr[e];
    }
#pragma unroll
    for (int e = 0; e < Ed; e++) {
#pragma unroll
        for (int o = 16; o > 0; o >>= 1)
            acc[e] += __shfl_xor_sync(0xffffffffu, acc[e], o);
    }

    if (lane == 0) {
        float l[Ed], p[Ed];
        float mx = -1e30f;
#pragma unroll
        for (int e = 0; e < Ed; e++) { l[e] = acc[e] + bg[e]; mx = fmaxf(mx, l[e]); }
        float s = 0.f;
#pragma unroll
        for (int e = 0; e < Ed; e++) { p[e] = expf(l[e] - mx); s += p[e]; }
#pragma unroll
        for (int e = 0; e < Ed; e++) p[e] /= s;
        float sum = 0.f;
#pragma unroll
        for (int e = 0; e < Ed; e++) sum += p[e];
        float inv = 1.0f / (sum + 1e-9f);

        bool used[Ed];
#pragma unroll
        for (int e = 0; e < Ed; e++) used[e] = false;
        for (int r = 0; r < Ed; r++) {
            int best = -1; float bv = -1e30f;
            for (int e = 0; e < Ed; e++)
                if (!used[e] && p[e] > bv) { bv = p[e]; best = e; }
            used[best] = true;
            g_order[t][r] = best;
            g_score[t][r] = bv * inv;
        }
    }
}

// ---------------------------------------------------------------------------
// Dispatch: buf[order[t][r]][t][:] = x[4t + r/2][:] * score[t][r]
// grid (Td, Ed), 256 threads, float4 copies.
// ---------------------------------------------------------------------------
__global__ void dispatch_kernel(const float* __restrict__ x) {
    int t = blockIdx.x;
    int r = blockIdx.y;
    int e = g_order[t][r];
    float sc = g_score[t][r];
    int src = 4 * t + (r >> 1);
    const float4* xs = (const float4*)(x + (size_t)src * Hd);
    float4* dst = (float4*)(g_buf + ((size_t)e * Td + t) * Hd);
    float4 v = xs[threadIdx.x];
    v.x *= sc; v.y *= sc; v.z *= sc; v.w *= sc;
    dst[threadIdx.x] = v;
}

// ---------------------------------------------------------------------------
// Tiled SGEMM: C[Td x Ndim] = A[Td x Kdim] @ B[Kdim x Ndim] + bias (, GELU)
// BM=BN=128, BK=8, 256 threads, 8x8 per-thread tile. blockIdx.z = expert.
// ---------------------------------------------------------------------------
__device__ __forceinline__ float gelu_exact(float v) {
    return 0.5f * v * (1.0f + erff(v * 0.70710678118654752f));
}

template <int Kdim, int Ndim, bool DoGelu>
__global__ __launch_bounds__(256)
void gemm_kernel(const float* __restrict__ A_, const float* __restrict__ B_,
                 const float* __restrict__ bias_, float* __restrict__ C_) {
    constexpr int BM = 128, BN = 128, BK = 8, TM = 8, TN = 8;
    const int e = blockIdx.z;
    const float* A = A_ + (size_t)e * Td * Kdim;
    const float* B = B_ + (size_t)e * Kdim * Ndim;
    const float* bias = bias_ + (size_t)e * Ndim;
    float* C = C_ + (size_t)e * Td * Ndim;

    __shared__ float As[BK][BM];
    __shared__ float Bs[BK][BN];

    const int bm = blockIdx.y * BM;
    const int bn = blockIdx.x * BN;
    const int tid = threadIdx.x;
    const int tx = tid & 15;          // 16 x 16 thread grid
    const int ty = tid >> 4;

    const int arow = tid >> 1;              // 0..127
    const int acol = (tid & 1) * 4;         // 0 or 4
    const int brow = tid >> 5;              // 0..7
    const int bcol = (tid & 31) * 4;        // 0..124

    float acc[TM][TN];
#pragma unroll
    for (int i = 0; i < TM; i++)
#pragma unroll
        for (int j = 0; j < TN; j++) acc[i][j] = 0.f;

    for (int k0 = 0; k0 < Kdim; k0 += BK) {
        float4 av = *(const float4*)(A + (size_t)(bm + arow) * Kdim + k0 + acol);
        As[acol + 0][arow] = av.x;
        As[acol + 1][arow] = av.y;
        As[acol + 2][arow] = av.z;
        As[acol + 3][arow] = av.w;
        float4 bv = *(const float4*)(B + (size_t)(k0 + brow) * Ndim + bn + bcol);
        *(float4*)&Bs[brow][bcol] = bv;
        __syncthreads();

#pragma unroll
        for (int k = 0; k < BK; k++) {
            float a[TM], b[TN];
#pragma unroll
            for (int i = 0; i < TM; i++) a[i] = As[k][ty * TM + i];
#pragma unroll
            for (int j = 0; j < TN; j++) b[j] = Bs[k][tx * TN + j];
#pragma unroll
            for (int i = 0; i < TM; i++)
#pragma unroll
                for (int j = 0; j < TN; j++) acc[i][j] = fmaf(a[i], b[j], acc[i][j]);
        }
        __syncthreads();
    }

#pragma unroll
    for (int i = 0; i < TM; i++) {
        int row = bm + ty * TM + i;
#pragma unroll
        for (int j = 0; j < TN; j += 4) {
            int col = bn + tx * TN + j;
            float4 v;
            v.x = acc[i][j + 0] + bias[col + 0];
            v.y = acc[i][j + 1] + bias[col + 1];
            v.z = acc[i][j + 2] + bias[col + 2];
            v.w = acc[i][j + 3] + bias[col + 3];
            if (DoGelu) {
                v.x = gelu_exact(v.x); v.y = gelu_exact(v.y);
                v.z = gelu_exact(v.z); v.w = gelu_exact(v.w);
            }
            *(float4*)(C + (size_t)row * Ndim + col) = v;
        }
    }
}

// ---------------------------------------------------------------------------
// Combine: y[m] = obuf[order[t][2q]][t] + obuf[order[t][2q+1]][t],
// t = m/4, q = m%4, for m in [0, 2048). (Remainder of output zeroed by memset.)
// ---------------------------------------------------------------------------
__global__ void combine_kernel(float* __restrict__ out) {
    int m = blockIdx.x;
    int t = m >> 2;
    int q = m & 3;
    int e1 = g_order[t][2 * q];
    int e2 = g_order[t][2 * q + 1];
    const float4* o1 = (const float4*)(g_obuf + ((size_t)e1 * Td + t) * Hd);
    const float4* o2 = (const float4*)(g_obuf + ((size_t)e2 * Td + t) * Hd);
    float4* dst = (float4*)(out + (size_t)m * Hd);
    float4 a = o1[threadIdx.x];
    float4 b = o2[threadIdx.x];
    float4 v; v.x = a.x + b.x; v.y = a.y + b.y; v.z = a.z + b.z; v.w = a.w + b.w;
    dst[threadIdx.x] = v;
}

// ---------------------------------------------------------------------------
extern "C" void kernel_launch(void* const* d_in, const int* in_sizes, int n_in,
                              void* d_out, int out_size) {
    (void)in_sizes; (void)n_in;
    const float* x  = (const float*)d_in[0];
    const float* Wg = (const float*)d_in[1];
    const float* bg = (const float*)d_in[2];
    const float* W1 = (const float*)d_in[3];
    const float* b1 = (const float*)d_in[4];
    const float* W2 = (const float*)d_in[5];
    const float* b2 = (const float*)d_in[6];
    float* out = (float*)d_out;

    // Zero everything past the nonzero region (incl. batches 1-3 and the
    // aux-loss scalar, which is exactly 0 under these shapes).
    size_t nz = (size_t)OUT_TOK * Hd;
    cudaMemsetAsync(out + nz, 0, ((size_t)out_size - nz) * sizeof(float), 0);

    gate_kernel<<<Td / 8, 256>>>(x, Wg, bg);
    dispatch_kernel<<<dim3(Td, Ed), 256>>>(x);

    float* buf;  cudaGetSymbolAddress((void**)&buf,  g_buf);
    float* hmid; cudaGetSymbolAddress((void**)&hmid, g_hmid);
    float* obuf; cudaGetSymbolAddress((void**)&obuf, g_obuf);

    // GEMM1 + GELU: (512 x 1024) @ (1024 x 4096) per expert
    gemm_kernel<Hd, Fd, true><<<dim3(Fd / 128, Td / 128, Ed), 256>>>(buf, W1, b1, hmid);
    // GEMM2: (512 x 4096) @ (4096 x 1024) per expert
    gemm_kernel<Fd, Hd, false><<<dim3(Hd / 128, Td / 128, Ed), 256>>>(hmid, W2, b2, obuf);

    combine_kernel<<<OUT_TOK, 256>>>(out);
}

// round 3
// speedup vs baseline: 2.2582x; 2.2582x over previous
#include <cuda_runtime.h>
#include <math.h>
#include <stdint.h>

// ---------------------------------------------------------------------------
// Shapes (fixed)
// ---------------------------------------------------------------------------
#define Hd 1024
#define Fd 4096
#define Ed 8
#define Td 512
#define OUT_TOK 2048

// ---------------------------------------------------------------------------
// Static device scratch (allocation-free per harness rules)
// ---------------------------------------------------------------------------
__device__ float g_buf [Ed * Td * Hd];                  // dispatched acts (tf32-rounded)
__device__ float g_hmid[(size_t)Ed * Td * Fd];          // GEMM1+GELU out (tf32-rounded)
__device__ float g_obuf[Ed * Td * Hd];                  // GEMM2 out (fp32)
__device__ float g_W1T [(size_t)Ed * Fd * Hd];          // W1^T [e][n][k] (tf32-rounded)
__device__ float g_W2T [(size_t)Ed * Hd * Fd];          // W2^T [e][h][f] (tf32-rounded)
__device__ int   g_order[Td][Ed];
__device__ float g_score[Td][Ed];

// ---------------------------------------------------------------------------
// Helpers
// ---------------------------------------------------------------------------
__device__ __forceinline__ uint32_t smem_u32(const void* p) {
    uint32_t a;
    asm("{ .reg .u64 t; cvta.to.shared.u64 t, %1; cvt.u32.u64 %0, t; }" : "=r"(a) : "l"(p));
    return a;
}
__device__ __forceinline__ float tf32r(float x) {
    uint32_t u;
    asm("cvt.rna.tf32.f32 %0, %1;" : "=r"(u) : "f"(x));
    return __uint_as_float(u);
}
__device__ __forceinline__ void cp_async16(uint32_t saddr, const void* gaddr) {
    asm volatile("cp.async.cg.shared.global [%0], [%1], 16;" :: "r"(saddr), "l"(gaddr));
}
__device__ __forceinline__ void cp_commit() {
    asm volatile("cp.async.commit_group;" ::: "memory");
}
__device__ __forceinline__ void cp_wait1() {
    asm volatile("cp.async.wait_group 1;" ::: "memory");
}
__device__ __forceinline__ void mma_tf32(float c[4], uint32_t a0, uint32_t a1,
                                         uint32_t a2, uint32_t a3,
                                         uint32_t b0, uint32_t b1) {
    asm volatile(
        "mma.sync.aligned.m16n8k8.row.col.f32.tf32.tf32.f32 "
        "{%0,%1,%2,%3}, {%4,%5,%6,%7}, {%8,%9}, {%0,%1,%2,%3};"
        : "+f"(c[0]), "+f"(c[1]), "+f"(c[2]), "+f"(c[3])
        : "r"(a0), "r"(a1), "r"(a2), "r"(a3), "r"(b0), "r"(b1));
}
__device__ __forceinline__ float gelu_exact(float v) {
    return 0.5f * v * (1.0f + erff(v * 0.70710678118654752f));
}

// ---------------------------------------------------------------------------
// Gating (unchanged from passing baseline)
// ---------------------------------------------------------------------------
__global__ void gate_kernel(const float* __restrict__ x,
                            const float* __restrict__ Wg,
                            const float* __restrict__ bg) {
    int warp = threadIdx.x >> 5;
    int lane = threadIdx.x & 31;
    int t = blockIdx.x * 8 + warp;
    if (t >= Td) return;

    const float* xr = x + (size_t)t * Hd;
    float acc[Ed];
#pragma unroll
    for (int e = 0; e < Ed; e++) acc[e] = 0.f;
    for (int h = lane; h < Hd; h += 32) {
        float xv = xr[h];
        const float* wr = Wg + (size_t)h * Ed;
#pragma unroll
        for (int e = 0; e < Ed; e++) acc[e] += xv * wr[e];
    }
#pragma unroll
    for (int e = 0; e < Ed; e++) {
#pragma unroll
        for (int o = 16; o > 0; o >>= 1)
            acc[e] += __shfl_xor_sync(0xffffffffu, acc[e], o);
    }
    if (lane == 0) {
        float l[Ed], p[Ed];
        float mx = -1e30f;
#pragma unroll
        for (int e = 0; e < Ed; e++) { l[e] = acc[e] + bg[e]; mx = fmaxf(mx, l[e]); }
        float s = 0.f;
#pragma unroll
        for (int e = 0; e < Ed; e++) { p[e] = expf(l[e] - mx); s += p[e]; }
#pragma unroll
        for (int e = 0; e < Ed; e++) p[e] /= s;
        float sum = 0.f;
#pragma unroll
        for (int e = 0; e < Ed; e++) sum += p[e];
        float inv = 1.0f / (sum + 1e-9f);
        bool used[Ed];
#pragma unroll
        for (int e = 0; e < Ed; e++) used[e] = false;
        for (int r = 0; r < Ed; r++) {
            int best = -1; float bv = -1e30f;
            for (int e = 0; e < Ed; e++)
                if (!used[e] && p[e] > bv) { bv = p[e]; best = e; }
            used[best] = true;
            g_order[t][r] = best;
            g_score[t][r] = bv * inv;
        }
    }
}

// ---------------------------------------------------------------------------
// Dispatch (tf32-rounds the MMA A operand)
// ---------------------------------------------------------------------------
__global__ void dispatch_kernel(const float* __restrict__ x) {
    int t = blockIdx.x;
    int r = blockIdx.y;
    int e = g_order[t][r];
    float sc = g_score[t][r];
    int src = 4 * t + (r >> 1);
    const float4* xs = (const float4*)(x + (size_t)src * Hd);
    float4* dst = (float4*)(g_buf + ((size_t)e * Td + t) * Hd);
    float4 v = xs[threadIdx.x];
    v.x = tf32r(v.x * sc); v.y = tf32r(v.y * sc);
    v.z = tf32r(v.z * sc); v.w = tf32r(v.w * sc);
    dst[threadIdx.x] = v;
}

// ---------------------------------------------------------------------------
// Weight pretranspose: in [E][R][C] -> out [E][C][R], tf32-rounded.
// ---------------------------------------------------------------------------
__global__ void transpose_kernel(const float* __restrict__ in, float* __restrict__ out,
                                 int R, int C) {
    __shared__ float tile[32][33];
    int e = blockIdx.z;
    const float* I = in + (size_t)e * R * C;
    float* O = out + (size_t)e * R * C;
    int c = blockIdx.x * 32 + threadIdx.x;
    int r0 = blockIdx.y * 32;
#pragma unroll
    for (int j = threadIdx.y; j < 32; j += 8)
        tile[j][threadIdx.x] = I[(size_t)(r0 + j) * C + c];
    __syncthreads();
    int rout = r0 + threadIdx.x;
    int c0 = blockIdx.x * 32;
#pragma unroll
    for (int j = threadIdx.y; j < 32; j += 8)
        O[(size_t)(c0 + j) * R + rout] = tf32r(tile[threadIdx.x][j]);
}

// ---------------------------------------------------------------------------
// tf32 mma.sync GEMM: C[e][Td x Ndim] = A[e][Td x Kdim] @ BT[e][Ndim x Kdim]^T
//  - BM=128 BN=128 BK=16, 3-stage cp.async pipeline, 256 threads
//  - warp grid 2x4, each warp 64x32 (4x4 mma tiles of m16n8k8)
//  - smem row stride 20 floats -> conflict-free fragment LDS
// ---------------------------------------------------------------------------
#define LDSSTR 20
#define TILE_WORDS (128 * LDSSTR)          // per-operand per-stage words
#define GEMM_SMEM_BYTES (2 * 3 * TILE_WORDS * 4)   // 61440

template <int Kdim, int Ndim, bool DoGelu>
__global__ __launch_bounds__(256, 2)
void gemm_mma(const float* __restrict__ A_, const float* __restrict__ B_,
              const float* __restrict__ bias_, float* __restrict__ C_) {
    constexpr int BK = 16;
    constexpr int NK = Kdim / BK;

    extern __shared__ float smem[];
    float* AsBase = smem;                       // [3][128][20]
    float* BsBase = smem + 3 * TILE_WORDS;      // [3][128][20]

    const int e  = blockIdx.z;
    const int m0 = blockIdx.y * 128;
    const int n0 = blockIdx.x * 128;
    const int tid = threadIdx.x;

    const float* Ag = A_ + (size_t)e * Td * Kdim;
    const float* Bg = B_ + (size_t)e * Ndim * Kdim;

    // loader: thread handles one half-row (32B) of A and of B per tile
    const int lrow = tid >> 1;                  // 0..127
    const int lcol = (tid & 1) * 8;             // 0 or 8
    const uint32_t sA0 = smem_u32(AsBase) + (uint32_t)(lrow * LDSSTR + lcol) * 4;
    const uint32_t sB0 = smem_u32(BsBase) + (uint32_t)(lrow * LDSSTR + lcol) * 4;
    const float* gA0 = Ag + (size_t)(m0 + lrow) * Kdim + lcol;
    const float* gB0 = Bg + (size_t)(n0 + lrow) * Kdim + lcol;

    auto load_stage = [&](int i) {
        int s = i % 3;
        uint32_t sa = sA0 + (uint32_t)(s * TILE_WORDS) * 4;
        uint32_t sb = sB0 + (uint32_t)(s * TILE_WORDS) * 4;
        const float* ga = gA0 + i * BK;
        const float* gb = gB0 + i * BK;
        cp_async16(sa, ga);
        cp_async16(sa + 16, ga + 4);
        cp_async16(sb, gb);
        cp_async16(sb + 16, gb + 4);
        cp_commit();
    };

    const int wid = tid >> 5;
    const int lane = tid & 31;
    const int wm = wid >> 2;                    // 0..1
    const int wn = wid & 3;                     // 0..3
    const int grp = lane >> 2;                  // 0..7
    const int tg  = lane & 3;                   // 0..3

    float c[4][4][4];
#pragma unroll
    for (int mt = 0; mt < 4; mt++)
#pragma unroll
        for (int nt = 0; nt < 4; nt++)
#pragma unroll
            for (int q = 0; q < 4; q++) c[mt][nt][q] = 0.f;

    load_stage(0);
    load_stage(1);

    for (int i = 0; i < NK; i++) {
        cp_wait1();
        __syncthreads();
        if (i + 2 < NK) load_stage(i + 2); else cp_commit();

        const uint32_t* as = (const uint32_t*)(AsBase + (i % 3) * TILE_WORDS);
        const uint32_t* bs = (const uint32_t*)(BsBase + (i % 3) * TILE_WORDS);

#pragma unroll
        for (int kk = 0; kk < 2; kk++) {
            const int kb = kk * 8 + tg;
            uint32_t a[4][4], b[4][2];
#pragma unroll
            for (int mt = 0; mt < 4; mt++) {
                int r = wm * 64 + mt * 16 + grp;
                a[mt][0] = as[r * LDSSTR + kb];
                a[mt][1] = as[(r + 8) * LDSSTR + kb];
                a[mt][2] = as[r * LDSSTR + kb + 4];
                a[mt][3] = as[(r + 8) * LDSSTR + kb + 4];
            }
#pragma unroll
            for (int nt = 0; nt < 4; nt++) {
                int cn = wn * 32 + nt * 8 + grp;
                b[nt][0] = bs[cn * LDSSTR + kb];
                b[nt][1] = bs[cn * LDSSTR + kb + 4];
            }
#pragma unroll
            for (int mt = 0; mt < 4; mt++)
#pragma unroll
                for (int nt = 0; nt < 4; nt++)
                    mma_tf32(c[mt][nt], a[mt][0], a[mt][1], a[mt][2], a[mt][3],
                             b[nt][0], b[nt][1]);
        }
    }

    // Epilogue: bias (+GELU +tf32 round), float2 stores
    const float* bias = bias_ + (size_t)e * Ndim + n0;
    float* C = C_ + (size_t)e * Td * Ndim;
#pragma unroll
    for (int mt = 0; mt < 4; mt++) {
        int r0 = m0 + wm * 64 + mt * 16 + grp;
#pragma unroll
        for (int nt = 0; nt < 4; nt++) {
            int col = wn * 32 + nt * 8 + tg * 2;
            float bx = bias[col], by = bias[col + 1];
            float2 v0, v1;
            v0.x = c[mt][nt][0] + bx;  v0.y = c[mt][nt][1] + by;
            v1.x = c[mt][nt][2] + bx;  v1.y = c[mt][nt][3] + by;
            if (DoGelu) {
                v0.x = tf32r(gelu_exact(v0.x)); v0.y = tf32r(gelu_exact(v0.y));
                v1.x = tf32r(gelu_exact(v1.x)); v1.y = tf32r(gelu_exact(v1.y));
            }
            *(float2*)(C + (size_t)r0 * Ndim + n0 + col) = v0;
            *(float2*)(C + (size_t)(r0 + 8) * Ndim + n0 + col) = v1;
        }
    }
}

// ---------------------------------------------------------------------------
// Combine (unchanged)
// ---------------------------------------------------------------------------
__global__ void combine_kernel(float* __restrict__ out) {
    int m = blockIdx.x;
    int t = m >> 2;
    int q = m & 3;
    int e1 = g_order[t][2 * q];
    int e2 = g_order[t][2 * q + 1];
    const float4* o1 = (const float4*)(g_obuf + ((size_t)e1 * Td + t) * Hd);
    const float4* o2 = (const float4*)(g_obuf + ((size_t)e2 * Td + t) * Hd);
    float4* dst = (float4*)(out + (size_t)m * Hd);
    float4 a = o1[threadIdx.x];
    float4 b = o2[threadIdx.x];
    float4 v; v.x = a.x + b.x; v.y = a.y + b.y; v.z = a.z + b.z; v.w = a.w + b.w;
    dst[threadIdx.x] = v;
}

// ---------------------------------------------------------------------------
extern "C" void kernel_launch(void* const* d_in, const int* in_sizes, int n_in,
                              void* d_out, int out_size) {
    (void)in_sizes; (void)n_in;
    const float* x  = (const float*)d_in[0];
    const float* Wg = (const float*)d_in[1];
    const float* bg = (const float*)d_in[2];
    const float* W1 = (const float*)d_in[3];
    const float* b1 = (const float*)d_in[4];
    const float* W2 = (const float*)d_in[5];
    const float* b2 = (const float*)d_in[6];
    float* out = (float*)d_out;

    float *buf, *hmid, *obuf, *w1t, *w2t;
    cudaGetSymbolAddress((void**)&buf,  g_buf);
    cudaGetSymbolAddress((void**)&hmid, g_hmid);
    cudaGetSymbolAddress((void**)&obuf, g_obuf);
    cudaGetSymbolAddress((void**)&w1t,  g_W1T);
    cudaGetSymbolAddress((void**)&w2t,  g_W2T);

    cudaFuncSetAttribute(gemm_mma<Hd, Fd, true>,
                         cudaFuncAttributeMaxDynamicSharedMemorySize, GEMM_SMEM_BYTES);
    cudaFuncSetAttribute(gemm_mma<Fd, Hd, false>,
                         cudaFuncAttributeMaxDynamicSharedMemorySize, GEMM_SMEM_BYTES);

    // Output tail (batches 1-3 + aux-loss scalar, all exactly zero)
    size_t nz = (size_t)OUT_TOK * Hd;
    cudaMemsetAsync(out + nz, 0, ((size_t)out_size - nz) * sizeof(float), 0);

    gate_kernel<<<Td / 8, 256>>>(x, Wg, bg);
    dispatch_kernel<<<dim3(Td, Ed), 256>>>(x);

    // Pretranspose (tf32-rounded): W1 [e][1024][4096] -> [e][4096][1024]
    transpose_kernel<<<dim3(Fd / 32, Hd / 32, Ed), dim3(32, 8)>>>(W1, w1t, Hd, Fd);
    // W2 [e][4096][1024] -> [e][1024][4096]
    transpose_kernel<<<dim3(Hd / 32, Fd / 32, Ed), dim3(32, 8)>>>(W2, w2t, Fd, Hd);

    // GEMM1 + GELU: per expert (512 x 1024) @ (1024 x 4096)
    gemm_mma<Hd, Fd, true><<<dim3(Fd / 128, Td / 128, Ed), 256, GEMM_SMEM_BYTES>>>(buf, w1t, b1, hmid);
    // GEMM2: per expert (512 x 4096) @ (4096 x 1024)
    gemm_mma<Fd, Hd, false><<<dim3(Hd / 128, Td / 128, Ed), 256, GEMM_SMEM_BYTES>>>(hmid, w2t, b2, obuf);

    combine_kernel<<<OUT_TOK, 256>>>(out);
}

// round 4
// speedup vs baseline: 2.7366x; 1.2118x over previous
#include <cuda_runtime.h>
#include <math.h>
#include <stdint.h>

// ---------------------------------------------------------------------------
// Shapes (fixed)
// ---------------------------------------------------------------------------
#define Hd 1024
#define Fd 4096
#define Ed 8
#define Td 512
#define OUT_TOK 2048

// ---------------------------------------------------------------------------
// Static device scratch (allocation-free per harness rules)
// ---------------------------------------------------------------------------
__device__ float g_buf [Ed * Td * Hd];                  // dispatched acts (tf32-rounded)
__device__ float g_hmid[(size_t)Ed * Td * Fd];          // GEMM1+GELU out (tf32-rounded)
__device__ float g_obuf[Ed * Td * Hd];                  // GEMM2 out (fp32)
__device__ int   g_order[Td][Ed];
__device__ float g_score[Td][Ed];

// ---------------------------------------------------------------------------
// Helpers
// ---------------------------------------------------------------------------
__device__ __forceinline__ uint32_t smem_u32(const void* p) {
    uint32_t a;
    asm("{ .reg .u64 t; cvta.to.shared.u64 t, %1; cvt.u32.u64 %0, t; }" : "=r"(a) : "l"(p));
    return a;
}
__device__ __forceinline__ float tf32r(float x) {
    uint32_t u;
    asm("cvt.rna.tf32.f32 %0, %1;" : "=r"(u) : "f"(x));
    return __uint_as_float(u);
}
__device__ __forceinline__ void cp_async16(uint32_t saddr, const void* gaddr) {
    asm volatile("cp.async.cg.shared.global [%0], [%1], 16;" :: "r"(saddr), "l"(gaddr));
}
__device__ __forceinline__ void cp_commit() {
    asm volatile("cp.async.commit_group;" ::: "memory");
}
__device__ __forceinline__ void cp_wait1() {
    asm volatile("cp.async.wait_group 1;" ::: "memory");
}
__device__ __forceinline__ void mma_tf32(float c[4], uint32_t a0, uint32_t a1,
                                         uint32_t a2, uint32_t a3,
                                         uint32_t b0, uint32_t b1) {
    asm volatile(
        "mma.sync.aligned.m16n8k8.row.col.f32.tf32.tf32.f32 "
        "{%0,%1,%2,%3}, {%4,%5,%6,%7}, {%8,%9}, {%0,%1,%2,%3};"
        : "+f"(c[0]), "+f"(c[1]), "+f"(c[2]), "+f"(c[3])
        : "r"(a0), "r"(a1), "r"(a2), "r"(a3), "r"(b0), "r"(b1));
}
__device__ __forceinline__ float gelu_exact(float v) {
    return 0.5f * v * (1.0f + erff(v * 0.70710678118654752f));
}

// ---------------------------------------------------------------------------
// Gating
// ---------------------------------------------------------------------------
__global__ void gate_kernel(const float* __restrict__ x,
                            const float* __restrict__ Wg,
                            const float* __restrict__ bg) {
    int warp = threadIdx.x >> 5;
    int lane = threadIdx.x & 31;
    int t = blockIdx.x * 8 + warp;
    if (t >= Td) return;

    const float* xr = x + (size_t)t * Hd;
    float acc[Ed];
#pragma unroll
    for (int e = 0; e < Ed; e++) acc[e] = 0.f;
    for (int h = lane; h < Hd; h += 32) {
        float xv = xr[h];
        const float* wr = Wg + (size_t)h * Ed;
#pragma unroll
        for (int e = 0; e < Ed; e++) acc[e] += xv * wr[e];
    }
#pragma unroll
    for (int e = 0; e < Ed; e++) {
#pragma unroll
        for (int o = 16; o > 0; o >>= 1)
            acc[e] += __shfl_xor_sync(0xffffffffu, acc[e], o);
    }
    if (lane == 0) {
        float l[Ed], p[Ed];
        float mx = -1e30f;
#pragma unroll
        for (int e = 0; e < Ed; e++) { l[e] = acc[e] + bg[e]; mx = fmaxf(mx, l[e]); }
        float s = 0.f;
#pragma unroll
        for (int e = 0; e < Ed; e++) { p[e] = expf(l[e] - mx); s += p[e]; }
#pragma unroll
        for (int e = 0; e < Ed; e++) p[e] /= s;
        float sum = 0.f;
#pragma unroll
        for (int e = 0; e < Ed; e++) sum += p[e];
        float inv = 1.0f / (sum + 1e-9f);
        bool used[Ed];
#pragma unroll
        for (int e = 0; e < Ed; e++) used[e] = false;
        for (int r = 0; r < Ed; r++) {
            int best = -1; float bv = -1e30f;
            for (int e = 0; e < Ed; e++)
                if (!used[e] && p[e] > bv) { bv = p[e]; best = e; }
            used[best] = true;
            g_order[t][r] = best;
            g_score[t][r] = bv * inv;
        }
    }
}

// ---------------------------------------------------------------------------
// Dispatch (tf32-rounds the MMA A operand)
// ---------------------------------------------------------------------------
__global__ void dispatch_kernel(const float* __restrict__ x) {
    int t = blockIdx.x;
    int r = blockIdx.y;
    int e = g_order[t][r];
    float sc = g_score[t][r];
    int src = 4 * t + (r >> 1);
    const float4* xs = (const float4*)(x + (size_t)src * Hd);
    float4* dst = (float4*)(g_buf + ((size_t)e * Td + t) * Hd);
    float4 v = xs[threadIdx.x];
    v.x = tf32r(v.x * sc); v.y = tf32r(v.y * sc);
    v.z = tf32r(v.z * sc); v.w = tf32r(v.w * sc);
    dst[threadIdx.x] = v;
}

// ---------------------------------------------------------------------------
// tf32 mma.sync GEMM: C[e][Td x Ndim] = A[e][Td x Kdim] @ B[e][Kdim x Ndim]
//  - B is consumed in its ORIGINAL [K][N] layout; transposed to K-major SMEM
//    during staging (coalesced LDG.32 + conflict-free STS.128, tf32-rounded).
//  - BM=128 BN=128 BK=16, A: 3-stage cp.async, B: 3-stage LDG->STS pipeline
//  - warp grid 2x4, each warp 64x32 (4x4 mma tiles of m16n8k8)
//  - smem row stride 20 floats -> conflict-free fragment LDS + STS.128
// ---------------------------------------------------------------------------
#define LDSSTR 20
#define TILE_WORDS (128 * LDSSTR)          // per-operand per-stage words
#define GEMM_SMEM_BYTES (2 * 3 * TILE_WORDS * 4)   // 61440

template <int Kdim, int Ndim, bool DoGelu>
__global__ __launch_bounds__(256, 2)
void gemm_mma(const float* __restrict__ A_, const float* __restrict__ B_,
              const float* __restrict__ bias_, float* __restrict__ C_) {
    constexpr int BK = 16;
    constexpr int NK = Kdim / BK;

    extern __shared__ float smem[];
    float* AsBase = smem;                       // [3][128][20]
    float* BsBase = smem + 3 * TILE_WORDS;      // [3][128 n][20 k]

    const int e  = blockIdx.z;
    const int m0 = blockIdx.y * 128;
    const int n0 = blockIdx.x * 128;
    const int tid = threadIdx.x;

    const float* Ag = A_ + (size_t)e * Td * Kdim;
    const float* BgE = B_ + (size_t)e * Kdim * Ndim;   // [K][N] row-major

    // ---- A loader (cp.async, K-major already) ----
    const int lrow = tid >> 1;                  // 0..127
    const int lcol = (tid & 1) * 8;             // 0 or 8
    const uint32_t sA0 = smem_u32(AsBase) + (uint32_t)(lrow * LDSSTR + lcol) * 4;
    const float* gA0 = Ag + (size_t)(m0 + lrow) * Kdim + lcol;

    auto cpA = [&](int i) {
        uint32_t sa = sA0 + (uint32_t)((i % 3) * TILE_WORDS) * 4;
        const float* ga = gA0 + i * BK;
        cp_async16(sa, ga);
        cp_async16(sa + 16, ga + 4);
        cp_commit();
    };

    // ---- B loader: thread covers column n_b, k-rows {4*kq..} and {4*kq+8..} ----
    const int n_b = tid & 127;
    const int kq  = tid >> 7;                   // 0..1
    const float* gB0 = BgE + (size_t)(kq * 4) * Ndim + n0 + n_b;
    float br[8];

    auto ldgB = [&](int i) {
        const float* p = gB0 + (size_t)(i * BK) * Ndim;
#pragma unroll
        for (int ii = 0; ii < 4; ii++) br[ii] = tf32r(p[(size_t)ii * Ndim]);
        const float* p2 = p + (size_t)8 * Ndim;
#pragma unroll
        for (int ii = 0; ii < 4; ii++) br[4 + ii] = tf32r(p2[(size_t)ii * Ndim]);
    };
    auto stsB = [&](int i) {
        float* bs = BsBase + (i % 3) * TILE_WORDS + n_b * LDSSTR + kq * 4;
        *(float4*)(bs)     = *(const float4*)&br[0];
        *(float4*)(bs + 8) = *(const float4*)&br[4];
    };

    // ---- warp/fragment mapping ----
    const int wid = tid >> 5;
    const int lane = tid & 31;
    const int wm = wid >> 2;                    // 0..1
    const int wn = wid & 3;                     // 0..3
    const int grp = lane >> 2;                  // 0..7
    const int tg  = lane & 3;                   // 0..3

    float c[4][4][4];
#pragma unroll
    for (int mt = 0; mt < 4; mt++)
#pragma unroll
        for (int nt = 0; nt < 4; nt++)
#pragma unroll
            for (int q = 0; q < 4; q++) c[mt][nt][q] = 0.f;

    // prologue: stages 0 and 1
    ldgB(0); stsB(0);
    ldgB(1); stsB(1);
    cpA(0);  cpA(1);

    for (int i = 0; i < NK; i++) {
        cp_wait1();
        __syncthreads();
        if (i + 2 < NK) { ldgB(i + 2); cpA(i + 2); }
        else cp_commit();

        const uint32_t* as = (const uint32_t*)(AsBase + (i % 3) * TILE_WORDS);
        const uint32_t* bs = (const uint32_t*)(BsBase + (i % 3) * TILE_WORDS);

#pragma unroll
        for (int kk = 0; kk < 2; kk++) {
            const int kb = kk * 8 + tg;
            uint32_t a[4][4], b[4][2];
#pragma unroll
            for (int mt = 0; mt < 4; mt++) {
                int r = wm * 64 + mt * 16 + grp;
                a[mt][0] = as[r * LDSSTR + kb];
                a[mt][1] = as[(r + 8) * LDSSTR + kb];
                a[mt][2] = as[r * LDSSTR + kb + 4];
                a[mt][3] = as[(r + 8) * LDSSTR + kb + 4];
            }
#pragma unroll
            for (int nt = 0; nt < 4; nt++) {
                int cn = wn * 32 + nt * 8 + grp;
                b[nt][0] = bs[cn * LDSSTR + kb];
                b[nt][1] = bs[cn * LDSSTR + kb + 4];
            }
#pragma unroll
            for (int mt = 0; mt < 4; mt++)
#pragma unroll
                for (int nt = 0; nt < 4; nt++)
                    mma_tf32(c[mt][nt], a[mt][0], a[mt][1], a[mt][2], a[mt][3],
                             b[nt][0], b[nt][1]);
        }

        if (i + 2 < NK) stsB(i + 2);   // safe: barrier above ensured all warps
                                       // finished reading this buffer (iter i-1)
    }

    // Epilogue: bias (+GELU +tf32 round), float2 stores
    const float* bias = bias_ + (size_t)e * Ndim + n0;
    float* C = C_ + (size_t)e * Td * Ndim;
#pragma unroll
    for (int mt = 0; mt < 4; mt++) {
        int r0 = m0 + wm * 64 + mt * 16 + grp;
#pragma unroll
        for (int nt = 0; nt < 4; nt++) {
            int col = wn * 32 + nt * 8 + tg * 2;
            float bx = bias[col], by = bias[col + 1];
            float2 v0, v1;
            v0.x = c[mt][nt][0] + bx;  v0.y = c[mt][nt][1] + by;
            v1.x = c[mt][nt][2] + bx;  v1.y = c[mt][nt][3] + by;
            if (DoGelu) {
                v0.x = tf32r(gelu_exact(v0.x)); v0.y = tf32r(gelu_exact(v0.y));
                v1.x = tf32r(gelu_exact(v1.x)); v1.y = tf32r(gelu_exact(v1.y));
            }
            *(float2*)(C + (size_t)r0 * Ndim + n0 + col) = v0;
            *(float2*)(C + (size_t)(r0 + 8) * Ndim + n0 + col) = v1;
        }
    }
}

// ---------------------------------------------------------------------------
// Combine
// ---------------------------------------------------------------------------
__global__ void combine_kernel(float* __restrict__ out) {
    int m = blockIdx.x;
    int t = m >> 2;
    int q = m & 3;
    int e1 = g_order[t][2 * q];
    int e2 = g_order[t][2 * q + 1];
    const float4* o1 = (const float4*)(g_obuf + ((size_t)e1 * Td + t) * Hd);
    const float4* o2 = (const float4*)(g_obuf + ((size_t)e2 * Td + t) * Hd);
    float4* dst = (float4*)(out + (size_t)m * Hd);
    float4 a = o1[threadIdx.x];
    float4 b = o2[threadIdx.x];
    float4 v; v.x = a.x + b.x; v.y = a.y + b.y; v.z = a.z + b.z; v.w = a.w + b.w;
    dst[threadIdx.x] = v;
}

// ---------------------------------------------------------------------------
extern "C" void kernel_launch(void* const* d_in, const int* in_sizes, int n_in,
                              void* d_out, int out_size) {
    (void)in_sizes; (void)n_in;
    const float* x  = (const float*)d_in[0];
    const float* Wg = (const float*)d_in[1];
    const float* bg = (const float*)d_in[2];
    const float* W1 = (const float*)d_in[3];
    const float* b1 = (const float*)d_in[4];
    const float* W2 = (const float*)d_in[5];
    const float* b2 = (const float*)d_in[6];
    float* out = (float*)d_out;

    float *buf, *hmid, *obuf;
    cudaGetSymbolAddress((void**)&buf,  g_buf);
    cudaGetSymbolAddress((void**)&hmid, g_hmid);
    cudaGetSymbolAddress((void**)&obuf, g_obuf);

    cudaFuncSetAttribute(gemm_mma<Hd, Fd, true>,
                         cudaFuncAttributeMaxDynamicSharedMemorySize, GEMM_SMEM_BYTES);
    cudaFuncSetAttribute(gemm_mma<Fd, Hd, false>,
                         cudaFuncAttributeMaxDynamicSharedMemorySize, GEMM_SMEM_BYTES);

    // Output tail (batches 1-3 + aux-loss scalar, all exactly zero)
    size_t nz = (size_t)OUT_TOK * Hd;
    cudaMemsetAsync(out + nz, 0, ((size_t)out_size - nz) * sizeof(float), 0);

    gate_kernel<<<Td / 8, 256>>>(x, Wg, bg);
    dispatch_kernel<<<dim3(Td, Ed), 256>>>(x);

    // GEMM1 + GELU: per expert (512 x 1024) @ (1024 x 4096), B in native layout
    gemm_mma<Hd, Fd, true><<<dim3(Fd / 128, Td / 128, Ed), 256, GEMM_SMEM_BYTES>>>(buf, W1, b1, hmid);
    // GEMM2: per expert (512 x 4096) @ (4096 x 1024), B in native layout
    gemm_mma<Fd, Hd, false><<<dim3(Hd / 128, Td / 128, Ed), 256, GEMM_SMEM_BYTES>>>(hmid, W2, b2, obuf);

    combine_kernel<<<OUT_TOK, 256>>>(out);
}